// round 2
// baseline (speedup 1.0000x reference)
#include <cuda_runtime.h>
#include <math.h>

#define H     24
#define LIMG  2048
#define LIP   512
#define DMOD  3072
#define DIP   1280
#define HD    128
#define LTOT  2560          // LIMG + LIP
#define SCALE 0.08838834764831845f   // 1/sqrt(128)

// ---------------- scratch (device globals; no allocs allowed) ----------------
__device__ float g_e[2 * DIP];                 // shift | scale
__device__ float g_ipnorm[LIP * DIP];
__device__ float g_ipk_raw[LIP * DMOD];
__device__ float g_Qn[(size_t)H * LIMG * HD];
__device__ float g_Kall[(size_t)H * LTOT * HD];
__device__ float g_Vall[(size_t)H * LTOT * HD];

// ---------------- stage 1: e = silu(t_emb) @ w_ada^T + b_ada ----------------
__global__ void ada_kernel(const float* __restrict__ t_emb,
                           const float* __restrict__ w_ada,
                           const float* __restrict__ b_ada) {
    int o = blockIdx.x * 8 + (threadIdx.x >> 5);
    int lane = threadIdx.x & 31;
    if (o >= 2 * DIP) return;
    const float* w = w_ada + (size_t)o * DIP;
    float s = 0.f;
    for (int i = lane; i < DIP; i += 32) {
        float t = t_emb[i];
        float si = t / (1.f + expf(-t));
        s += si * w[i];
    }
#pragma unroll
    for (int off = 16; off; off >>= 1) s += __shfl_xor_sync(0xffffffffu, s, off);
    if (lane == 0) g_e[o] = s + b_ada[o];
}

// ---------------- stage 2: AdaLayerNorm on ip_hidden_states ----------------
__global__ void adaln_kernel(const float* __restrict__ ip) {
    int row = blockIdx.x;                   // 0..511
    const float* x = ip + (size_t)row * DIP;
    __shared__ float red1[8], red2[8];
    float s = 0.f, s2 = 0.f;
    for (int i = threadIdx.x; i < DIP; i += 256) {
        float v = x[i];
        s += v; s2 += v * v;
    }
#pragma unroll
    for (int off = 16; off; off >>= 1) {
        s  += __shfl_xor_sync(0xffffffffu, s, off);
        s2 += __shfl_xor_sync(0xffffffffu, s2, off);
    }
    int w = threadIdx.x >> 5, lane = threadIdx.x & 31;
    if (lane == 0) { red1[w] = s; red2[w] = s2; }
    __syncthreads();
    float ts = 0.f, ts2 = 0.f;
#pragma unroll
    for (int i = 0; i < 8; i++) { ts += red1[i]; ts2 += red2[i]; }
    float mu  = ts / DIP;
    float var = ts2 / DIP - mu * mu;
    float inv = rsqrtf(var + 1e-6f);
    for (int i = threadIdx.x; i < DIP; i += 256) {
        float xn = (x[i] - mu) * inv;
        g_ipnorm[(size_t)row * DIP + i] = xn * (1.f + g_e[DIP + i]) + g_e[i];
    }
}

// ---------------- stage 3: ip_key / ip_value GEMMs (512x3072x1280) ----------
__global__ void ip_gemm_kernel(const float* __restrict__ wk,
                               const float* __restrict__ wv) {
    const float* W = blockIdx.z ? wv : wk;
    int bn = blockIdx.x * 64, bm = blockIdx.y * 64;
    __shared__ float As[64][17], Bs[64][17];
    float acc[4][4] = {};
    int tx = threadIdx.x & 15, ty = threadIdx.x >> 4;
    for (int k0 = 0; k0 < DIP; k0 += 16) {
        for (int i = threadIdx.x; i < 64 * 16; i += 256) {
            int rr = i >> 4, cc = i & 15;
            As[rr][cc] = g_ipnorm[(size_t)(bm + rr) * DIP + k0 + cc];
            Bs[rr][cc] = W[(size_t)(bn + rr) * DIP + k0 + cc];
        }
        __syncthreads();
#pragma unroll
        for (int kk = 0; kk < 16; kk++) {
            float a[4], b[4];
#pragma unroll
            for (int i = 0; i < 4; i++) a[i] = As[ty * 4 + i][kk];
#pragma unroll
            for (int j = 0; j < 4; j++) b[j] = Bs[tx * 4 + j][kk];
#pragma unroll
            for (int i = 0; i < 4; i++)
#pragma unroll
                for (int j = 0; j < 4; j++) acc[i][j] = fmaf(a[i], b[j], acc[i][j]);
        }
        __syncthreads();
    }
#pragma unroll
    for (int i = 0; i < 4; i++)
#pragma unroll
        for (int j = 0; j < 4; j++) {
            int m = bm + ty * 4 + i, n = bn + tx * 4 + j;
            if (blockIdx.z == 0) {
                g_ipk_raw[(size_t)m * DMOD + n] = acc[i][j];
            } else {
                int hh = n >> 7, dd = n & 127;
                g_Vall[((size_t)hh * LTOT + LIMG + m) * HD + dd] = acc[i][j];
            }
        }
}

// ---------------- stage 4: RMSNorm q,k + copy v into head-major layout ------
__device__ __forceinline__ float warp_sum(float s) {
#pragma unroll
    for (int off = 16; off; off >>= 1) s += __shfl_xor_sync(0xffffffffu, s, off);
    return s;
}

__global__ void qkv_rms_kernel(const float* __restrict__ q,
                               const float* __restrict__ k,
                               const float* __restrict__ v,
                               const float* __restrict__ gq,
                               const float* __restrict__ gk) {
    int rid = blockIdx.x * 8 + (threadIdx.x >> 5);
    if (rid >= LIMG * H) return;
    int lane = threadIdx.x & 31;
    int l = rid / H, hh = rid % H;
    size_t src = (size_t)l * DMOD + hh * HD + lane * 4;

    // q
    float4 xv = *(const float4*)(q + src);
    float ss = warp_sum(xv.x * xv.x + xv.y * xv.y + xv.z * xv.z + xv.w * xv.w);
    float inv = rsqrtf(ss / 128.f + 1e-6f);
    float4 gv = ((const float4*)gq)[lane];
    float4 o  = { xv.x * inv * gv.x, xv.y * inv * gv.y, xv.z * inv * gv.z, xv.w * inv * gv.w };
    *(float4*)(g_Qn + ((size_t)hh * LIMG + l) * HD + lane * 4) = o;

    // k
    xv = *(const float4*)(k + src);
    ss = warp_sum(xv.x * xv.x + xv.y * xv.y + xv.z * xv.z + xv.w * xv.w);
    inv = rsqrtf(ss / 128.f + 1e-6f);
    gv = ((const float4*)gk)[lane];
    o = make_float4(xv.x * inv * gv.x, xv.y * inv * gv.y, xv.z * inv * gv.z, xv.w * inv * gv.w);
    *(float4*)(g_Kall + ((size_t)hh * LTOT + l) * HD + lane * 4) = o;

    // v (plain copy)
    *(float4*)(g_Vall + ((size_t)hh * LTOT + l) * HD + lane * 4) = *(const float4*)(v + src);
}

__global__ void ipk_rms_kernel(const float* __restrict__ gipk) {
    int rid = blockIdx.x * 8 + (threadIdx.x >> 5);
    if (rid >= LIP * H) return;
    int lane = threadIdx.x & 31;
    int l = rid / H, hh = rid % H;
    float4 xv = *(const float4*)(g_ipk_raw + (size_t)l * DMOD + hh * HD + lane * 4);
    float ss = warp_sum(xv.x * xv.x + xv.y * xv.y + xv.z * xv.z + xv.w * xv.w);
    float inv = rsqrtf(ss / 128.f + 1e-6f);
    float4 gv = ((const float4*)gipk)[lane];
    float4 o  = { xv.x * inv * gv.x, xv.y * inv * gv.y, xv.z * inv * gv.z, xv.w * inv * gv.w };
    *(float4*)(g_Kall + ((size_t)hh * LTOT + LIMG + l) * HD + lane * 4) = o;
}

// ---------------- stage 5: flash attention (fp32, M=64, Ktile=32) -----------
// smem floats: Q 64*132, K 32*132, V 32*132, P 64*33
#define Q_STRIDE 132
#define ATTN_SMEM_FLOATS (64 * 132 + 32 * 132 + 32 * 132 + 64 * 33)

__global__ void attn_kernel(float* __restrict__ out) {
    extern __shared__ float smem[];
    float* Qs = smem;
    float* Ks = Qs + 64 * 132;
    float* Vs = Ks + 32 * 132;
    float* Ps = Vs + 32 * 132;

    const int hh  = blockIdx.y;
    const int q0  = blockIdx.x * 64;
    const int tid = threadIdx.x;
    const int r   = tid >> 2;    // row within tile (0..63)
    const int qg  = tid & 3;     // quarter

    // load + pre-scale Q tile
    const float4* Qb = (const float4*)(g_Qn + ((size_t)hh * LIMG + q0) * HD);
    for (int i = tid; i < 64 * 32; i += 256) {
        int rr = i >> 5, c4 = i & 31;
        float4 v = Qb[rr * 32 + c4];
        v.x *= SCALE; v.y *= SCALE; v.z *= SCALE; v.w *= SCALE;
        ((float4*)(Qs + rr * 132))[c4] = v;
    }

    float m = -1e30f, lsum = 0.f;
    float4 acc[8];
#pragma unroll
    for (int j = 0; j < 8; j++) acc[j] = make_float4(0.f, 0.f, 0.f, 0.f);
    __syncthreads();

    const float4* Kh = (const float4*)(g_Kall + (size_t)hh * LTOT * HD);
    const float4* Vh = (const float4*)(g_Vall + (size_t)hh * LTOT * HD);

    for (int kt = 0; kt < LTOT; kt += 32) {
        for (int i = tid; i < 32 * 32; i += 256) {
            int rr = i >> 5, c4 = i & 31;
            ((float4*)(Ks + rr * 132))[c4] = Kh[(size_t)(kt + rr) * 32 + c4];
            ((float4*)(Vs + rr * 132))[c4] = Vh[(size_t)(kt + rr) * 32 + c4];
        }
        __syncthreads();

        // S: this thread handles keys (j*4 + qg), j=0..7, for row r
        float s[8];
#pragma unroll
        for (int j = 0; j < 8; j++) s[j] = 0.f;
        const float4* Qr = (const float4*)(Qs + r * 132);
        for (int d4 = 0; d4 < 32; d4++) {
            float4 qv = Qr[d4];
#pragma unroll
            for (int j = 0; j < 8; j++) {
                float4 kv = ((const float4*)(Ks + (j * 4 + qg) * 132))[d4];
                s[j] = fmaf(qv.x, kv.x, fmaf(qv.y, kv.y, fmaf(qv.z, kv.z, fmaf(qv.w, kv.w, s[j]))));
            }
        }

        // online softmax (4 lanes share row r)
        float mt = s[0];
#pragma unroll
        for (int j = 1; j < 8; j++) mt = fmaxf(mt, s[j]);
        mt = fmaxf(mt, __shfl_xor_sync(0xffffffffu, mt, 1));
        mt = fmaxf(mt, __shfl_xor_sync(0xffffffffu, mt, 2));
        float mnew = fmaxf(m, mt);
        float corr = __expf(m - mnew);
        float ps = 0.f;
#pragma unroll
        for (int j = 0; j < 8; j++) { s[j] = __expf(s[j] - mnew); ps += s[j]; }
        ps += __shfl_xor_sync(0xffffffffu, ps, 1);
        ps += __shfl_xor_sync(0xffffffffu, ps, 2);
        lsum = lsum * corr + ps;
        m = mnew;
#pragma unroll
        for (int j = 0; j < 8; j++) {
            acc[j].x *= corr; acc[j].y *= corr; acc[j].z *= corr; acc[j].w *= corr;
        }
#pragma unroll
        for (int j = 0; j < 8; j++) Ps[r * 33 + j * 4 + qg] = s[j];
        __syncwarp();   // Ps row r written only by this warp's 4-lane group

        // O += P @ V ; this thread owns col chunks (j*4+qg)*4..+4
        for (int kk = 0; kk < 32; kk++) {
            float p = Ps[r * 33 + kk];
            const float4* Vr = (const float4*)(Vs + kk * 132);
#pragma unroll
            for (int j = 0; j < 8; j++) {
                float4 vv = Vr[j * 4 + qg];
                acc[j].x = fmaf(p, vv.x, acc[j].x);
                acc[j].y = fmaf(p, vv.y, acc[j].y);
                acc[j].z = fmaf(p, vv.z, acc[j].z);
                acc[j].w = fmaf(p, vv.w, acc[j].w);
            }
        }
        __syncthreads();  // protect Ks/Vs before next tile load
    }

    float invl = 1.f / lsum;
    float* op = out + (size_t)(q0 + r) * DMOD + hh * HD;
#pragma unroll
    for (int j = 0; j < 8; j++) {
        float4 o = { acc[j].x * invl, acc[j].y * invl, acc[j].z * invl, acc[j].w * invl };
        ((float4*)op)[j * 4 + qg] = o;
    }
}

// ---------------- launch -----------------------------------------------------
extern "C" void kernel_launch(void* const* d_in, const int* in_sizes, int n_in,
                              void* d_out, int out_size) {
    const float* ip   = (const float*)d_in[0];
    const float* q    = (const float*)d_in[1];
    const float* k    = (const float*)d_in[2];
    const float* v    = (const float*)d_in[3];
    const float* temb = (const float*)d_in[4];
    const float* wada = (const float*)d_in[5];
    const float* bada = (const float*)d_in[6];
    const float* wk   = (const float*)d_in[7];
    const float* wv   = (const float*)d_in[8];
    const float* gq   = (const float*)d_in[9];
    const float* gk   = (const float*)d_in[10];
    const float* gipk = (const float*)d_in[11];
    float* out = (float*)d_out;

    ada_kernel<<<(2 * DIP + 7) / 8, 256>>>(temb, wada, bada);
    adaln_kernel<<<LIP, 256>>>(ip);
    ip_gemm_kernel<<<dim3(DMOD / 64, LIP / 64, 2), 256>>>(wk, wv);
    qkv_rms_kernel<<<(LIMG * H + 7) / 8, 256>>>(q, k, v, gq, gk);
    ipk_rms_kernel<<<(LIP * H + 7) / 8, 256>>>(gipk);

    int smem_bytes = ATTN_SMEM_FLOATS * (int)sizeof(float);   // 76032
    cudaFuncSetAttribute(attn_kernel, cudaFuncAttributeMaxDynamicSharedMemorySize, smem_bytes);
    attn_kernel<<<dim3(LIMG / 64, H), 256, smem_bytes>>>(out);
}